// round 8
// baseline (speedup 1.0000x reference)
#include <cuda_runtime.h>
#include <stdint.h>

#define F_IN  512
#define F_HID 128
#define F_OUT 64
#define N_MAX 100000
#define E_MAX 1600000

// ---------------- scratch (device globals; no allocation allowed) ----------
__device__ int   g_is64;
__device__ int   g_deg   [N_MAX];
__device__ int   g_cursor[N_MAX];
__device__ int   g_off   [N_MAX + 1];
__device__ float g_dinv  [N_MAX];
__device__ int   g_csr_src[E_MAX];
__device__ float g_csr_w  [E_MAX];
__device__ float g_h1  [(size_t)N_MAX * F_HID];
__device__ float g_a1  [(size_t)N_MAX * F_HID];
__device__ float g_h2  [(size_t)N_MAX * F_OUT];

// ---------------- edge-index dtype detection --------------------------------
__global__ void detect_kernel(const int* __restrict__ w, int n_words) {
    __shared__ int any;
    if (threadIdx.x == 0) any = 0;
    __syncthreads();
    int lim = min(2048, n_words / 2);
    for (int i = threadIdx.x; i < lim; i += blockDim.x)
        if (w[2 * i + 1] != 0) any = 1;
    __syncthreads();
    if (threadIdx.x == 0) g_is64 = (any == 0);
}
__device__ __forceinline__ int edge_at(const void* ei, long long idx) {
    if (g_is64) return (int)((const long long*)ei)[idx];
    return ((const int*)ei)[idx];
}

// ---------------- degree / normalization / CSR build -------------------------
__global__ void deg_init(int N) {
    int i = blockIdx.x * blockDim.x + threadIdx.x;
    if (i < N) { g_deg[i] = 1; g_cursor[i] = 0; }
}
__global__ void deg_count(const void* __restrict__ ei, int E) {
    int e = blockIdx.x * blockDim.x + threadIdx.x;
    if (e >= E) return;
    atomicAdd(&g_deg[edge_at(ei, (long long)E + e)], 1);
}
__global__ void dinv_kernel(int N) {
    int i = blockIdx.x * blockDim.x + threadIdx.x;
    if (i < N) g_dinv[i] = rsqrtf((float)g_deg[i]);
}
__global__ void scan_kernel(int N, int E) {
    __shared__ int sh[1024];
    int tid = threadIdx.x;
    int chunk = (N + 1023) >> 10;
    int st = tid * chunk, en = min(st + chunk, N);
    int s = 0;
    for (int i = st; i < en; i++) s += g_deg[i] - 1;
    sh[tid] = s;
    __syncthreads();
    for (int off = 1; off < 1024; off <<= 1) {
        int v = (tid >= off) ? sh[tid - off] : 0;
        __syncthreads();
        sh[tid] += v;
        __syncthreads();
    }
    int base = tid ? sh[tid - 1] : 0;
    for (int i = st; i < en; i++) { g_off[i] = base; base += g_deg[i] - 1; }
    if (tid == 0) g_off[N] = E;
}
__global__ void place_kernel(const void* __restrict__ ei, int E) {
    int e = blockIdx.x * blockDim.x + threadIdx.x;
    if (e >= E) return;
    int src = edge_at(ei, e);
    int dst = edge_at(ei, (long long)E + e);
    int pos = g_off[dst] + atomicAdd(&g_cursor[dst], 1);
    g_csr_src[pos] = src;
    g_csr_w[pos]   = g_dinv[src] * g_dinv[dst];
}

// ---------------- TF32 tensor-core GEMM (pipelined, race-fixed) --------------
__device__ __forceinline__ uint32_t tf32_of(float x) {
    uint32_t u;
    asm("cvt.rna.tf32.f32 %0, %1;" : "=r"(u) : "f"(x));
    return u;
}
__device__ __forceinline__ void mma_tf32(float* d, const uint32_t* a, const uint32_t* b) {
    asm volatile(
        "mma.sync.aligned.m16n8k8.row.col.f32.tf32.tf32.f32 "
        "{%0,%1,%2,%3}, {%4,%5,%6,%7}, {%8,%9}, {%0,%1,%2,%3};"
        : "+f"(d[0]), "+f"(d[1]), "+f"(d[2]), "+f"(d[3])
        : "r"(a[0]), "r"(a[1]), "r"(a[2]), "r"(a[3]), "r"(b[0]), "r"(b[1]));
}
__device__ __forceinline__ void cp_async16(void* smem_dst, const void* gsrc) {
    uint32_t s = (uint32_t)__cvta_generic_to_shared(smem_dst);
    asm volatile("cp.async.ca.shared.global [%0], [%1], 16;" :: "r"(s), "l"(gsrc));
}
__device__ __forceinline__ void cp_commit() { asm volatile("cp.async.commit_group;"); }
template <int NN> __device__ __forceinline__ void cp_wait() {
    asm volatile("cp.async.wait_group %0;" :: "n"(NN));
}

// C[M,N] = A[M,K] @ B[K,N], row-major. 256 threads. N%BN==0, K%BK==0, BK==32.
// A packed in smem in mma-fragment order (tf32), lane^ks swizzled.
// B staged raw via cp.async (padded rows), tf32-rounded at fragment load.
// Hazard discipline: ALL cross-stage smem writes (cpB, stsA) are issued only
// after the iteration's cp_wait + __syncthreads, which orders them after every
// other warp's reads of that stage in the previous iteration.
template <int BM, int BN, int WM, int WN>
__global__ __launch_bounds__(256, 2) void mma_gemm(const float* __restrict__ A,
                                                   const float* __restrict__ B,
                                                   float* __restrict__ C,
                                                   int M, int N, int K) {
    constexpr int BK = 32;
    constexpr int KS = BK / 8;          // 4
    constexpr int WARPS_N = BN / WN;
    constexpr int MI = WM / 16;
    constexpr int NI = WN / 8;
    constexpr int AW = (BM / 16) * KS * 128;      // words per A stage
    constexpr int BROW = BN + 8;
    constexpr int BW = BK * BROW;                 // words per B stage
    constexpr int NA4 = BM * BK / 4 / 256;        // float4 per thread (A)
    constexpr int NB4 = BK * BN / 4 / 256;        // float4 per thread (B)

    extern __shared__ uint32_t smem[];
    uint32_t* Asm = smem;                     // 2 stages of AW
    float*    Bsm = (float*)(smem + 2 * AW);  // 2 stages of BW

    const int tid  = threadIdx.x;
    const int lane = tid & 31;
    const int w    = tid >> 5;
    const int wm   = w / WARPS_N;
    const int wn   = w % WARPS_N;
    const int bm0  = blockIdx.x * BM;
    const int bn0  = blockIdx.y * BN;

    float acc[MI][NI][4];
#pragma unroll
    for (int i = 0; i < MI; i++)
#pragma unroll
        for (int j = 0; j < NI; j++)
#pragma unroll
            for (int k = 0; k < 4; k++) acc[i][j][k] = 0.f;

    float4 areg[NA4];

    auto ldgA = [&](int k0) {
#pragma unroll
        for (int j = 0; j < NA4; j++) {
            int i  = tid + j * 256;
            int r  = i / (BK / 4);
            int c4 = (i % (BK / 4)) * 4;
            int gr = bm0 + r;
            areg[j] = make_float4(0.f, 0.f, 0.f, 0.f);
            if (gr < M) areg[j] = *(const float4*)(A + (size_t)gr * K + k0 + c4);
        }
    };
    auto stsA = [&](int stg) {
        uint32_t* dst = Asm + stg * AW;
#pragma unroll
        for (int j = 0; j < NA4; j++) {
            int i   = tid + j * 256;
            int r   = i / (BK / 4);
            int c4  = (i % (BK / 4)) * 4;
            int m16 = r >> 4, rr = r & 15;
            int ks  = c4 >> 3, g = (c4 >> 2) & 1;
            const float* v = (const float*)&areg[j];
#pragma unroll
            for (int jj = 0; jj < 4; jj++) {
                int ln   = ((rr & 7) << 2) | jj;
                int slot = (rr >> 3) | (g << 1);
                dst[((m16 * KS + ks) << 7) + ((ln ^ ks) << 2) + slot] = tf32_of(v[jj]);
            }
        }
    };
    auto cpB = [&](int k0, int stg) {
        float* dst = Bsm + stg * BW;
#pragma unroll
        for (int j = 0; j < NB4; j++) {
            int i  = tid + j * 256;
            int r  = i / (BN / 4);
            int c4 = (i % (BN / 4)) * 4;
            cp_async16(dst + r * BROW + c4, B + (size_t)(k0 + r) * N + bn0 + c4);
        }
        cp_commit();
    };

    const int T = K / BK;

    // prologue: stage 0 (no one is reading yet, safe before any sync)
    ldgA(0);
    cpB(0, 0);
    stsA(0);

    for (int t = 0; t < T; t++) {
        const int cur = t & 1, nxt = cur ^ 1;
        const bool more = (t + 1 < T);

        if (more) ldgA((t + 1) * BK);       // global -> regs, no smem hazard
        cp_wait<0>();                       // B stage `cur` data landed
        __syncthreads();                    // + all reads of stage `nxt` (iter t-1) done
        if (more) cpB((t + 1) * BK, nxt);   // NOW safe to overwrite stage `nxt`

        const uint32_t* Asp = Asm + cur * AW;
        const float*    Bsp = Bsm + cur * BW;
#pragma unroll
        for (int ks = 0; ks < KS; ks++) {
            uint32_t af[MI][4], bf[NI][2];
#pragma unroll
            for (int mi = 0; mi < MI; mi++) {
                const uint32_t* p = Asp + (((wm * MI + mi) * KS + ks) << 7) + ((lane ^ ks) << 2);
                uint4 u = *(const uint4*)p;
                af[mi][0] = u.x; af[mi][1] = u.y; af[mi][2] = u.z; af[mi][3] = u.w;
            }
            const int br = ks * 8 + (lane & 3);
#pragma unroll
            for (int ni = 0; ni < NI; ni++) {
                int n0 = wn * WN + ni * 8 + (lane >> 2);
                bf[ni][0] = tf32_of(Bsp[br * BROW + n0]);
                bf[ni][1] = tf32_of(Bsp[(br + 4) * BROW + n0]);
            }
#pragma unroll
            for (int mi = 0; mi < MI; mi++)
#pragma unroll
                for (int ni = 0; ni < NI; ni++)
                    mma_tf32(acc[mi][ni], af[mi], bf[ni]);
        }
        if (more) stsA(nxt);   // reads of stage nxt (iter t-1) were fenced by this
                               // iteration's __syncthreads; reads of this data occur
                               // after next iteration's __syncthreads.
    }

    // epilogue
#pragma unroll
    for (int mi = 0; mi < MI; mi++) {
#pragma unroll
        for (int ni = 0; ni < NI; ni++) {
            int r0 = bm0 + wm * WM + mi * 16 + (lane >> 2);
            int cc = bn0 + wn * WN + ni * 8 + (lane & 3) * 2;
            if (r0 < M)
                *(float2*)(C + (size_t)r0 * N + cc) = make_float2(acc[mi][ni][0], acc[mi][ni][1]);
            if (r0 + 8 < M)
                *(float2*)(C + (size_t)(r0 + 8) * N + cc) = make_float2(acc[mi][ni][2], acc[mi][ni][3]);
        }
    }
}

// ---------------- gather aggregation (warp per node) --------------------------
template <int F, bool RELU>
__global__ __launch_bounds__(256) void gather_agg(const float* __restrict__ h,
                                                  const float* __restrict__ bias,
                                                  float* __restrict__ outp, int N) {
    int node = blockIdx.x * (blockDim.x >> 5) + (threadIdx.x >> 5);
    if (node >= N) return;
    int lane = threadIdx.x & 31;
    int e = g_off[node], e1 = g_off[node + 1];
    float dn = g_dinv[node];
    float sw = dn * dn;

    if (F == 128) {
        const float4* hp = (const float4*)h;
        float4 acc = hp[(size_t)node * 32 + lane];
        acc.x *= sw; acc.y *= sw; acc.z *= sw; acc.w *= sw;
        for (; e + 4 <= e1; e += 4) {
            int s0 = g_csr_src[e], s1 = g_csr_src[e + 1];
            int s2 = g_csr_src[e + 2], s3 = g_csr_src[e + 3];
            float w0 = g_csr_w[e], w1 = g_csr_w[e + 1];
            float w2 = g_csr_w[e + 2], w3 = g_csr_w[e + 3];
            float4 v0 = hp[(size_t)s0 * 32 + lane];
            float4 v1 = hp[(size_t)s1 * 32 + lane];
            float4 v2 = hp[(size_t)s2 * 32 + lane];
            float4 v3 = hp[(size_t)s3 * 32 + lane];
            acc.x += w0 * v0.x + w1 * v1.x + w2 * v2.x + w3 * v3.x;
            acc.y += w0 * v0.y + w1 * v1.y + w2 * v2.y + w3 * v3.y;
            acc.z += w0 * v0.z + w1 * v1.z + w2 * v2.z + w3 * v3.z;
            acc.w += w0 * v0.w + w1 * v1.w + w2 * v2.w + w3 * v3.w;
        }
        for (; e < e1; e++) {
            int s = g_csr_src[e];
            float wv = g_csr_w[e];
            float4 v = hp[(size_t)s * 32 + lane];
            acc.x += wv * v.x; acc.y += wv * v.y; acc.z += wv * v.z; acc.w += wv * v.w;
        }
        float4 b = ((const float4*)bias)[lane];
        acc.x += b.x; acc.y += b.y; acc.z += b.z; acc.w += b.w;
        if (RELU) {
            acc.x = fmaxf(acc.x, 0.f); acc.y = fmaxf(acc.y, 0.f);
            acc.z = fmaxf(acc.z, 0.f); acc.w = fmaxf(acc.w, 0.f);
        }
        ((float4*)outp)[(size_t)node * 32 + lane] = acc;
    } else {  // F == 64
        const float2* hp = (const float2*)h;
        float2 acc = hp[(size_t)node * 32 + lane];
        acc.x *= sw; acc.y *= sw;
        for (; e + 4 <= e1; e += 4) {
            int s0 = g_csr_src[e], s1 = g_csr_src[e + 1];
            int s2 = g_csr_src[e + 2], s3 = g_csr_src[e + 3];
            float w0 = g_csr_w[e], w1 = g_csr_w[e + 1];
            float w2 = g_csr_w[e + 2], w3 = g_csr_w[e + 3];
            float2 v0 = hp[(size_t)s0 * 32 + lane];
            float2 v1 = hp[(size_t)s1 * 32 + lane];
            float2 v2 = hp[(size_t)s2 * 32 + lane];
            float2 v3 = hp[(size_t)s3 * 32 + lane];
            acc.x += w0 * v0.x + w1 * v1.x + w2 * v2.x + w3 * v3.x;
            acc.y += w0 * v0.y + w1 * v1.y + w2 * v2.y + w3 * v3.y;
        }
        for (; e < e1; e++) {
            int s = g_csr_src[e];
            float wv = g_csr_w[e];
            float2 v = hp[(size_t)s * 32 + lane];
            acc.x += wv * v.x; acc.y += wv * v.y;
        }
        float2 b = ((const float2*)bias)[lane];
        acc.x += b.x; acc.y += b.y;
        if (RELU) { acc.x = fmaxf(acc.x, 0.f); acc.y = fmaxf(acc.y, 0.f); }
        ((float2*)outp)[(size_t)node * 32 + lane] = acc;
    }
}

// ---------------- launch -----------------------------------------------------
extern "C" void kernel_launch(void* const* d_in, const int* in_sizes, int n_in,
                              void* d_out, int out_size) {
    const float* x  = (const float*)d_in[0];
    const void*  ei = d_in[1];
    const float* W1 = (const float*)d_in[2];
    const float* b1 = (const float*)d_in[3];
    const float* W2 = (const float*)d_in[4];
    const float* b2 = (const float*)d_in[5];
    float* out = (float*)d_out;

    const int N = in_sizes[0] / F_IN;
    const int E = in_sizes[1] / 2;

    float *h1p, *a1p, *h2p;
    cudaGetSymbolAddress((void**)&h1p, g_h1);
    cudaGetSymbolAddress((void**)&a1p, g_a1);
    cudaGetSymbolAddress((void**)&h2p, g_h2);

    const int smem1 = (2 * (128 / 16) * 4 * 128 + 2 * 32 * (128 + 8)) * 4;  // 67584
    const int smem2 = (2 * (128 / 16) * 4 * 128 + 2 * 32 * (64 + 8)) * 4;   // 51200
    cudaFuncSetAttribute((const void*)mma_gemm<128, 128, 64, 32>,
                         cudaFuncAttributeMaxDynamicSharedMemorySize, smem1);
    cudaFuncSetAttribute((const void*)mma_gemm<128, 64, 32, 32>,
                         cudaFuncAttributeMaxDynamicSharedMemorySize, smem2);

    detect_kernel<<<1, 256>>>((const int*)ei, in_sizes[1]);
    deg_init<<<(N + 255) / 256, 256>>>(N);
    deg_count<<<(E + 255) / 256, 256>>>(ei, E);
    dinv_kernel<<<(N + 255) / 256, 256>>>(N);
    scan_kernel<<<1, 1024>>>(N, E);
    place_kernel<<<(E + 255) / 256, 256>>>(ei, E);

    // Layer 1: h1 = x @ W1 ; a1 = relu(A_norm h1 + b1)
    mma_gemm<128, 128, 64, 32><<<dim3((N + 127) / 128, F_HID / 128), 256, smem1>>>(
        x, W1, h1p, N, F_HID, F_IN);
    gather_agg<F_HID, true><<<(N + 7) / 8, 256>>>(h1p, b1, a1p, N);

    // Layer 2: h2 = a1 @ W2 ; out = A_norm h2 + b2
    mma_gemm<128, 64, 32, 32><<<dim3((N + 127) / 128, F_OUT / 64), 256, smem2>>>(
        a1p, W2, h2p, N, F_OUT, F_HID);
    gather_agg<F_OUT, false><<<(N + 7) / 8, 256>>>(h2p, b2, out, N);
}

// round 9
// speedup vs baseline: 1.3312x; 1.3312x over previous
#include <cuda_runtime.h>
#include <stdint.h>

#define F_IN  512
#define F_HID 128
#define F_OUT 64
#define N_MAX 100000
#define E_MAX 1600000

// ---------------- scratch (device globals; no allocation allowed) ----------
__device__ int   g_is64;
__device__ int   g_deg   [N_MAX];
__device__ int   g_cursor[N_MAX];
__device__ int   g_off   [N_MAX + 1];
__device__ float g_dinv  [N_MAX];
__device__ int   g_csr_src[E_MAX];
__device__ float g_csr_w  [E_MAX];
__device__ float g_h1  [(size_t)N_MAX * F_HID];
__device__ float g_a1  [(size_t)N_MAX * F_HID];
__device__ float g_h2  [(size_t)N_MAX * F_OUT];

// ---------------- init + edge-index dtype detection (merged) -----------------
// int64 non-negative values < 2^31  =>  every odd 32-bit word is 0.
__global__ void init_detect(const int* __restrict__ w, int n_words, int N) {
    int i = blockIdx.x * blockDim.x + threadIdx.x;
    if (i < N) { g_deg[i] = 1; g_cursor[i] = 0; }   // self-loop counted
    if (blockIdx.x == 0) {
        __shared__ int any;
        if (threadIdx.x == 0) any = 0;
        __syncthreads();
        int lim = min(2048, n_words / 2);
        for (int j = threadIdx.x; j < lim; j += blockDim.x)
            if (w[2 * j + 1] != 0) any = 1;   // benign race
        __syncthreads();
        if (threadIdx.x == 0) g_is64 = (any == 0);
    }
}
__device__ __forceinline__ int edge_at(const void* ei, long long idx) {
    if (g_is64) return (int)((const long long*)ei)[idx];
    return ((const int*)ei)[idx];
}

// ---------------- degree / scan(+dinv) / CSR build ---------------------------
__global__ void deg_count(const void* __restrict__ ei, int E) {
    int e = blockIdx.x * blockDim.x + threadIdx.x;
    if (e >= E) return;
    atomicAdd(&g_deg[edge_at(ei, (long long)E + e)], 1);
}
__global__ void scan_kernel(int N, int E) {
    __shared__ int sh[1024];
    int tid = threadIdx.x;
    int chunk = (N + 1023) >> 10;
    int st = tid * chunk, en = min(st + chunk, N);
    int s = 0;
    for (int i = st; i < en; i++) s += g_deg[i] - 1;
    sh[tid] = s;
    __syncthreads();
    for (int off = 1; off < 1024; off <<= 1) {
        int v = (tid >= off) ? sh[tid - off] : 0;
        __syncthreads();
        sh[tid] += v;
        __syncthreads();
    }
    int base = tid ? sh[tid - 1] : 0;
    for (int i = st; i < en; i++) {
        g_off[i] = base;
        int d = g_deg[i];
        base += d - 1;
        g_dinv[i] = rsqrtf((float)d);
    }
    if (tid == 0) g_off[N] = E;
}
__global__ void place_kernel(const void* __restrict__ ei, int E) {
    int e = blockIdx.x * blockDim.x + threadIdx.x;
    if (e >= E) return;
    int src = edge_at(ei, e);
    int dst = edge_at(ei, (long long)E + e);
    int pos = g_off[dst] + atomicAdd(&g_cursor[dst], 1);
    g_csr_src[pos] = src;
    g_csr_w[pos]   = g_dinv[src] * g_dinv[dst];
}

// ---------------- TF32 tensor-core GEMM (cp.async double-buffered) -----------
__device__ __forceinline__ uint32_t tf32_of(float x) {
    uint32_t u;
    asm("cvt.rna.tf32.f32 %0, %1;" : "=r"(u) : "f"(x));
    return u;
}
__device__ __forceinline__ void mma_tf32(float* d, const uint32_t* a, const uint32_t* b) {
    asm volatile(
        "mma.sync.aligned.m16n8k8.row.col.f32.tf32.tf32.f32 "
        "{%0,%1,%2,%3}, {%4,%5,%6,%7}, {%8,%9}, {%0,%1,%2,%3};"
        : "+f"(d[0]), "+f"(d[1]), "+f"(d[2]), "+f"(d[3])
        : "r"(a[0]), "r"(a[1]), "r"(a[2]), "r"(a[3]), "r"(b[0]), "r"(b[1]));
}
__device__ __forceinline__ void cp_async16(void* smem_dst, const void* gsrc) {
    uint32_t s = (uint32_t)__cvta_generic_to_shared(smem_dst);
    asm volatile("cp.async.ca.shared.global [%0], [%1], 16;" :: "r"(s), "l"(gsrc));
}
// zero-fill variant: src-size 0 -> writes 16 zero bytes, no global read
__device__ __forceinline__ void cp_async16z(void* smem_dst, const void* gsrc, bool valid) {
    uint32_t s = (uint32_t)__cvta_generic_to_shared(smem_dst);
    int sz = valid ? 16 : 0;
    asm volatile("cp.async.ca.shared.global [%0], [%1], 16, %2;"
                 :: "r"(s), "l"(gsrc), "r"(sz));
}
__device__ __forceinline__ void cp_commit() { asm volatile("cp.async.commit_group;"); }
template <int NN> __device__ __forceinline__ void cp_wait() {
    asm volatile("cp.async.wait_group %0;" :: "n"(NN));
}

// C[M,N] = A[M,K] @ B[K,N], row-major. 256 threads. N%BN==0, K%32==0.
// Raw float tiles staged via cp.async (double-buffered, padded rows);
// tf32 rounding happens at fragment-load time. One __syncthreads per k-tile.
// Hazard: stage `nxt` cp.asyncs are issued only after this iteration's
// cp_wait+__syncthreads, which orders them after all reads of that stage
// from the previous iteration. cp_wait precedes the barrier so the barrier
// publishes every thread's completed copies.
template <int BM, int BN, int WM, int WN>
__global__ __launch_bounds__(256, 2) void mma_gemm(const float* __restrict__ A,
                                                   const float* __restrict__ B,
                                                   float* __restrict__ C,
                                                   int M, int N, int K) {
    constexpr int BK = 32;
    constexpr int KS = BK / 8;                // 4
    constexpr int WARPS_N = BN / WN;
    constexpr int MI = WM / 16;
    constexpr int NI = WN / 8;
    constexpr int AROW = BK + 4;              // 36 words; banks (4r+c) distinct
    constexpr int AW = BM * AROW;
    constexpr int BROW = BN + 8;              // ≡8 mod 32; banks (8br+n) distinct
    constexpr int BW = BK * BROW;
    constexpr int NA4 = BM * BK / 4 / 256;    // 4
    constexpr int NB4 = BK * BN / 4 / 256;    // 4 (BN=128) / 2 (BN=64)

    extern __shared__ float smem[];
    float* Asm = smem;                 // 2 stages of AW
    float* Bsm = smem + 2 * AW;        // 2 stages of BW

    const int tid  = threadIdx.x;
    const int lane = tid & 31;
    const int w    = tid >> 5;
    const int wm   = w / WARPS_N;
    const int wn   = w % WARPS_N;
    const int bm0  = blockIdx.x * BM;
    const int bn0  = blockIdx.y * BN;

    float acc[MI][NI][4];
#pragma unroll
    for (int i = 0; i < MI; i++)
#pragma unroll
        for (int j = 0; j < NI; j++)
#pragma unroll
            for (int k = 0; k < 4; k++) acc[i][j][k] = 0.f;

    auto cpA = [&](int k0, int stg) {
        float* dst = Asm + stg * AW;
#pragma unroll
        for (int j = 0; j < NA4; j++) {
            int i  = tid + j * 256;
            int r  = i / (BK / 4);
            int c4 = (i % (BK / 4)) * 4;
            int gr = bm0 + r;
            bool ok = (gr < M);
            const float* src = A + (size_t)(ok ? gr : 0) * K + k0 + c4;
            cp_async16z(dst + r * AROW + c4, src, ok);
        }
    };
    auto cpB = [&](int k0, int stg) {
        float* dst = Bsm + stg * BW;
#pragma unroll
        for (int j = 0; j < NB4; j++) {
            int i  = tid + j * 256;
            int r  = i / (BN / 4);
            int c4 = (i % (BN / 4)) * 4;
            cp_async16(dst + r * BROW + c4, B + (size_t)(k0 + r) * N + bn0 + c4);
        }
    };

    const int T = K / BK;

    cpA(0, 0); cpB(0, 0); cp_commit();

    for (int t = 0; t < T; t++) {
        const int cur = t & 1, nxt = cur ^ 1;
        const bool more = (t + 1 < T);

        cp_wait<0>();          // own copies for stage `cur` done
        __syncthreads();       // all threads' copies done; prior reads of `nxt` done
        if (more) { cpA((t + 1) * BK, nxt); cpB((t + 1) * BK, nxt); cp_commit(); }

        const float* Asp = Asm + cur * AW;
        const float* Bsp = Bsm + cur * BW;
#pragma unroll
        for (int ks = 0; ks < KS; ks++) {
            uint32_t af[MI][4], bf[NI][2];
            const int c = ks * 8 + (lane & 3);
#pragma unroll
            for (int mi = 0; mi < MI; mi++) {
                int r0 = wm * WM + mi * 16 + (lane >> 2);
                af[mi][0] = tf32_of(Asp[r0 * AROW + c]);
                af[mi][1] = tf32_of(Asp[(r0 + 8) * AROW + c]);
                af[mi][2] = tf32_of(Asp[r0 * AROW + c + 4]);
                af[mi][3] = tf32_of(Asp[(r0 + 8) * AROW + c + 4]);
            }
#pragma unroll
            for (int ni = 0; ni < NI; ni++) {
                int n0 = wn * WN + ni * 8 + (lane >> 2);
                bf[ni][0] = tf32_of(Bsp[c * BROW + n0]);          // br == c
                bf[ni][1] = tf32_of(Bsp[(c + 4) * BROW + n0]);
            }
#pragma unroll
            for (int mi = 0; mi < MI; mi++)
#pragma unroll
                for (int ni = 0; ni < NI; ni++)
                    mma_tf32(acc[mi][ni], af[mi], bf[ni]);
        }
    }

    // epilogue
#pragma unroll
    for (int mi = 0; mi < MI; mi++) {
#pragma unroll
        for (int ni = 0; ni < NI; ni++) {
            int r0 = bm0 + wm * WM + mi * 16 + (lane >> 2);
            int cc = bn0 + wn * WN + ni * 8 + (lane & 3) * 2;
            if (r0 < M)
                *(float2*)(C + (size_t)r0 * N + cc) = make_float2(acc[mi][ni][0], acc[mi][ni][1]);
            if (r0 + 8 < M)
                *(float2*)(C + (size_t)(r0 + 8) * N + cc) = make_float2(acc[mi][ni][2], acc[mi][ni][3]);
        }
    }
}

// ---------------- gather aggregation (warp per node) --------------------------
template <int F, bool RELU>
__global__ __launch_bounds__(256) void gather_agg(const float* __restrict__ h,
                                                  const float* __restrict__ bias,
                                                  float* __restrict__ outp, int N) {
    int node = blockIdx.x * (blockDim.x >> 5) + (threadIdx.x >> 5);
    if (node >= N) return;
    int lane = threadIdx.x & 31;
    int e = g_off[node], e1 = g_off[node + 1];
    float dn = g_dinv[node];
    float sw = dn * dn;

    if (F == 128) {
        const float4* hp = (const float4*)h;
        float4 acc = hp[(size_t)node * 32 + lane];
        acc.x *= sw; acc.y *= sw; acc.z *= sw; acc.w *= sw;
        for (; e + 4 <= e1; e += 4) {
            int s0 = g_csr_src[e], s1 = g_csr_src[e + 1];
            int s2 = g_csr_src[e + 2], s3 = g_csr_src[e + 3];
            float w0 = g_csr_w[e], w1 = g_csr_w[e + 1];
            float w2 = g_csr_w[e + 2], w3 = g_csr_w[e + 3];
            float4 v0 = hp[(size_t)s0 * 32 + lane];
            float4 v1 = hp[(size_t)s1 * 32 + lane];
            float4 v2 = hp[(size_t)s2 * 32 + lane];
            float4 v3 = hp[(size_t)s3 * 32 + lane];
            acc.x += w0 * v0.x + w1 * v1.x + w2 * v2.x + w3 * v3.x;
            acc.y += w0 * v0.y + w1 * v1.y + w2 * v2.y + w3 * v3.y;
            acc.z += w0 * v0.z + w1 * v1.z + w2 * v2.z + w3 * v3.z;
            acc.w += w0 * v0.w + w1 * v1.w + w2 * v2.w + w3 * v3.w;
        }
        for (; e < e1; e++) {
            int s = g_csr_src[e];
            float wv = g_csr_w[e];
            float4 v = hp[(size_t)s * 32 + lane];
            acc.x += wv * v.x; acc.y += wv * v.y; acc.z += wv * v.z; acc.w += wv * v.w;
        }
        float4 b = ((const float4*)bias)[lane];
        acc.x += b.x; acc.y += b.y; acc.z += b.z; acc.w += b.w;
        if (RELU) {
            acc.x = fmaxf(acc.x, 0.f); acc.y = fmaxf(acc.y, 0.f);
            acc.z = fmaxf(acc.z, 0.f); acc.w = fmaxf(acc.w, 0.f);
        }
        ((float4*)outp)[(size_t)node * 32 + lane] = acc;
    } else {  // F == 64
        const float2* hp = (const float2*)h;
        float2 acc = hp[(size_t)node * 32 + lane];
        acc.x *= sw; acc.y *= sw;
        for (; e + 4 <= e1; e += 4) {
            int s0 = g_csr_src[e], s1 = g_csr_src[e + 1];
            int s2 = g_csr_src[e + 2], s3 = g_csr_src[e + 3];
            float w0 = g_csr_w[e], w1 = g_csr_w[e + 1];
            float w2 = g_csr_w[e + 2], w3 = g_csr_w[e + 3];
            float2 v0 = hp[(size_t)s0 * 32 + lane];
            float2 v1 = hp[(size_t)s1 * 32 + lane];
            float2 v2 = hp[(size_t)s2 * 32 + lane];
            float2 v3 = hp[(size_t)s3 * 32 + lane];
            acc.x += w0 * v0.x + w1 * v1.x + w2 * v2.x + w3 * v3.x;
            acc.y += w0 * v0.y + w1 * v1.y + w2 * v2.y + w3 * v3.y;
        }
        for (; e < e1; e++) {
            int s = g_csr_src[e];
            float wv = g_csr_w[e];
            float2 v = hp[(size_t)s * 32 + lane];
            acc.x += wv * v.x; acc.y += wv * v.y;
        }
        float2 b = ((const float2*)bias)[lane];
        acc.x += b.x; acc.y += b.y;
        if (RELU) { acc.x = fmaxf(acc.x, 0.f); acc.y = fmaxf(acc.y, 0.f); }
        ((float2*)outp)[(size_t)node * 32 + lane] = acc;
    }
}

// ---------------- launch -----------------------------------------------------
extern "C" void kernel_launch(void* const* d_in, const int* in_sizes, int n_in,
                              void* d_out, int out_size) {
    const float* x  = (const float*)d_in[0];
    const void*  ei = d_in[1];
    const float* W1 = (const float*)d_in[2];
    const float* b1 = (const float*)d_in[3];
    const float* W2 = (const float*)d_in[4];
    const float* b2 = (const float*)d_in[5];
    float* out = (float*)d_out;

    const int N = in_sizes[0] / F_IN;
    const int E = in_sizes[1] / 2;

    float *h1p, *a1p, *h2p;
    cudaGetSymbolAddress((void**)&h1p, g_h1);
    cudaGetSymbolAddress((void**)&a1p, g_a1);
    cudaGetSymbolAddress((void**)&h2p, g_h2);

    // smem: 2 A-stages (BM*(BK+4)) + 2 B-stages (BK*(BN+8)), in bytes
    const int smem1 = (2 * 128 * 36 + 2 * 32 * 136) * 4;  // 71680
    const int smem2 = (2 * 128 * 36 + 2 * 32 * 72) * 4;   // 55296
    cudaFuncSetAttribute((const void*)mma_gemm<128, 128, 64, 32>,
                         cudaFuncAttributeMaxDynamicSharedMemorySize, smem1);
    cudaFuncSetAttribute((const void*)mma_gemm<128, 64, 32, 32>,
                         cudaFuncAttributeMaxDynamicSharedMemorySize, smem2);

    init_detect<<<(N + 255) / 256, 256>>>((const int*)ei, in_sizes[1], N);
    deg_count<<<(E + 255) / 256, 256>>>(ei, E);
    scan_kernel<<<1, 1024>>>(N, E);
    place_kernel<<<(E + 255) / 256, 256>>>(ei, E);

    // Layer 1: h1 = x @ W1 ; a1 = relu(A_norm h1 + b1)
    mma_gemm<128, 128, 64, 32><<<dim3((N + 127) / 128, F_HID / 128), 256, smem1>>>(
        x, W1, h1p, N, F_HID, F_IN);
    gather_agg<F_HID, true><<<(N + 7) / 8, 256>>>(h1p, b1, a1p, N);

    // Layer 2: h2 = a1 @ W2 ; out = A_norm h2 + b2
    mma_gemm<128, 64, 32, 32><<<dim3((N + 127) / 128, F_OUT / 64), 256, smem2>>>(
        a1p, W2, h2p, N, F_OUT, F_HID);
    gather_agg<F_OUT, false><<<(N + 7) / 8, 256>>>(h2p, b2, out, N);
}